// round 4
// baseline (speedup 1.0000x reference)
#include <cuda_runtime.h>
#include <cmath>
#include <complex>
#include <cstring>

// Problem constants
#define TT   50
#define PAD  49
#define EXT  148              // PAD + TT + PAD
#define BB   50
#define CC   4096
#define BC   (BB * CC)        // 204800 channels
#define NSEC 2
#define NBAND 2
#define BLK  64               // threads per block (one channel per thread)

struct FiltCoef {
    // [band][section]
    float b0[NBAND][NSEC];
    float b2[NBAND][NSEC];
    float a1[NBAND][NSEC];
    float a2[NBAND][NSEC];
    float zi0[NBAND][NSEC];
    float zi1[NBAND][NSEC];
};

// per-band, per-channel normalization stats (channel index = b*C + c)
__device__ float g_m2 [NBAND][BC];
__device__ float g_inv[NBAND][BC];

__global__ void __launch_bounds__(BLK)
filtfilt_kernel(const float* __restrict__ x, float* __restrict__ out, FiltCoef cf) {
    __shared__ float sm[EXT * BLK];
    const int tid  = threadIdx.x;
    const int ch   = blockIdx.x * BLK + tid;   // channel index in [0, BC)
    const int band = blockIdx.y;
    float* col = sm + tid;                     // thread-private column, stride BLK

    // ---- build odd extension in smem ----
    #pragma unroll 5
    for (int t = 0; t < TT; t++)
        col[(PAD + t) * BLK] = x[(size_t)t * BC + ch];

    const float x0 = col[PAD * BLK];
    const float xl = col[(PAD + TT - 1) * BLK];
    #pragma unroll 7
    for (int k = 1; k <= PAD; k++) {
        col[(PAD - k) * BLK]          = 2.0f * x0 - col[(PAD + k) * BLK];
        col[(PAD + TT - 1 + k) * BLK] = 2.0f * xl - col[(PAD + TT - 1 - k) * BLK];
    }

    const float b00 = cf.b0[band][0], b20 = cf.b2[band][0];
    const float a10 = cf.a1[band][0], a20 = cf.a2[band][0];
    const float b01 = cf.b0[band][1], b21 = cf.b2[band][1];
    const float a11 = cf.a1[band][1], a21 = cf.a2[band][1];

    // ---- forward pass (2 cascaded biquads, DF2T) ----
    {
        const float e0 = col[0];
        float z00 = cf.zi0[band][0] * e0, z01 = cf.zi1[band][0] * e0;
        float z10 = cf.zi0[band][1] * e0, z11 = cf.zi1[band][1] * e0;
        float* p = col;
        #pragma unroll 4
        for (int t = 0; t < EXT; t++) {
            const float xt = *p;
            const float y0 = fmaf(b00, xt, z00);
            z00 = fmaf(-a10, y0, z01);
            z01 = fmaf(b20, xt, -a20 * y0);
            const float y1 = fmaf(b01, y0, z10);
            z10 = fmaf(-a11, y1, z11);
            z11 = fmaf(b21, y0, -a21 * y1);
            *p = y1;
            p += BLK;
        }
    }

    // ---- backward pass (filter the reversed signal, in place) ----
    {
        const float yl = col[(EXT - 1) * BLK];
        float z00 = cf.zi0[band][0] * yl, z01 = cf.zi1[band][0] * yl;
        float z10 = cf.zi0[band][1] * yl, z11 = cf.zi1[band][1] * yl;
        float* p = col + (EXT - 1) * BLK;
        #pragma unroll 4
        for (int t = 0; t < EXT; t++) {
            const float xt = *p;
            const float y0 = fmaf(b00, xt, z00);
            z00 = fmaf(-a10, y0, z01);
            z01 = fmaf(b20, xt, -a20 * y0);
            const float y1 = fmaf(b01, y0, z10);
            z10 = fmaf(-a11, y1, z11);
            z11 = fmaf(b21, y0, -a21 * y1);
            *p = y1;
            p -= BLK;
        }
    }

    // ---- first demean over T (per-channel) ----
    float s = 0.0f;
    #pragma unroll 10
    for (int t = 0; t < TT; t++) s += col[(PAD + t) * BLK];
    const float m = s * (1.0f / TT);

    // yd = y - m ; store yd to out; compute m2 = mean(yd), v = sum((yd-m2)^2)
    float s2 = 0.0f;
    float* ob = out + (size_t)band * TT * BC + ch;
    #pragma unroll 10
    for (int t = 0; t < TT; t++) {
        const float yd = col[(PAD + t) * BLK] - m;
        col[(PAD + t) * BLK] = yd;
        ob[(size_t)t * BC] = yd;
        s2 += yd;
    }
    const float m2 = s2 * (1.0f / TT);

    float v = 0.0f;
    #pragma unroll 10
    for (int t = 0; t < TT; t++) {
        const float d = col[(PAD + t) * BLK] - m2;
        v = fmaf(d, d, v);
    }
    g_m2 [band][ch] = m2;
    g_inv[band][ch] = rsqrtf(v * (1.0f / (TT - 1)));
}

// out[band, t, b, c] = (yd[band, t, b, c] - m2[band, t*C+c]) * inv_s[band, t*C+c]
// (stats indexed by TIME index t, mirroring the reference's broadcasting quirk; T==B)
__global__ void __launch_bounds__(256)
normalize_kernel(float* __restrict__ out) {
    const int idx = blockIdx.x * 256 + threadIdx.x;   // < NBAND*TT*BC
    const int c    = idx & (CC - 1);
    const int rest = idx / BC;            // band*TT + t
    const int t    = rest % TT;
    const int band = rest / TT;
    const int sidx = t * CC + c;          // channel (b'=t, c)
    out[idx] = (out[idx] - g_m2[band][sidx]) * g_inv[band][sidx];
}

// ---------------- host-side filter design (mirrors reference numpy code) ----------------
static void design_band(double w1, double w2, double sos[NSEC][6], double zi[NSEC][2]) {
    using cd = std::complex<double>;
    const double PI = 3.14159265358979323846;
    const double fs = 2.0;
    const double W1 = 2.0 * fs * tan(PI * w1 / fs);
    const double W2 = 2.0 * fs * tan(PI * w2 / fs);
    const double bw = W2 - W1;
    const double wo = sqrt(W1 * W2);

    cd p_bp[4];
    for (int k = 1; k <= 2; k++) {
        cd p = -std::exp(cd(0.0, PI * (2 * k - 1) / 4.0));
        cd plp = p * (bw / 2.0);
        cd disc = std::sqrt(plp * plp - cd(wo * wo, 0.0));
        p_bp[k - 1] = plp + disc;   // order matches np.concatenate([p_lp+disc, p_lp-disc])
        p_bp[k + 1] = plp - disc;
    }
    const double fs2 = 2.0 * fs;   // 4.0
    cd prod(1.0, 0.0);
    for (int i = 0; i < 4; i++) prod *= (cd(fs2, 0.0) - p_bp[i]);
    const double gain = bw * bw * fs2 * fs2 / prod.real();

    cd pos[2];
    int npos = 0;
    for (int i = 0; i < 4; i++) {
        cd pd = (cd(fs2, 0.0) + p_bp[i]) / (cd(fs2, 0.0) - p_bp[i]);
        if (pd.imag() > 0.0 && npos < 2) pos[npos++] = pd;
    }
    for (int s = 0; s < NSEC; s++) {
        const double g = (s == 0) ? gain : 1.0;
        sos[s][0] = g;  sos[s][1] = 0.0;  sos[s][2] = -g;
        sos[s][3] = 1.0;
        sos[s][4] = -2.0 * pos[s].real();
        sos[s][5] = std::norm(pos[s]);
    }
    // sosfilt_zi
    double scale = 1.0;
    for (int s = 0; s < NSEC; s++) {
        const double b0 = sos[s][0], b1 = sos[s][1], b2 = sos[s][2];
        const double a1 = sos[s][4], a2 = sos[s][5];
        const double B0 = b1 - a1 * b0;
        const double B1 = b2 - a2 * b0;
        const double det = 1.0 + a1 + a2;
        zi[s][0] = scale * (B0 + B1) / det;
        zi[s][1] = scale * ((1.0 + a1) * B1 - a2 * B0) / det;
        scale *= (b0 + b1 + b2) / (1.0 + a1 + a2);
    }
}

extern "C" void kernel_launch(void* const* d_in, const int* in_sizes, int n_in,
                              void* d_out, int out_size) {
    const float* x = (const float*)d_in[0];
    float* out = (float*)d_out;

    const double bands[NBAND][2] = { {0.05, 0.15}, {0.2, 0.4} };
    FiltCoef cf;
    for (int b = 0; b < NBAND; b++) {
        double sos[NSEC][6], zi[NSEC][2];
        design_band(bands[b][0], bands[b][1], sos, zi);
        for (int s = 0; s < NSEC; s++) {
            cf.b0[b][s]  = (float)sos[s][0];
            cf.b2[b][s]  = (float)sos[s][2];
            cf.a1[b][s]  = (float)sos[s][4];
            cf.a2[b][s]  = (float)sos[s][5];
            cf.zi0[b][s] = (float)zi[s][0];
            cf.zi1[b][s] = (float)zi[s][1];
        }
    }

    dim3 grid1(BC / BLK, NBAND);            // 3200 x 2
    filtfilt_kernel<<<grid1, BLK>>>(x, out, cf);

    const int total = NBAND * TT * BC;      // 20,480,000
    normalize_kernel<<<total / 256, 256>>>(out);
}

// round 6
// speedup vs baseline: 1.1185x; 1.1185x over previous
#include <cuda_runtime.h>
#include <cmath>
#include <complex>
#include <cstring>

// Problem constants
#define TT   50
#define PAD  49
#define EXT  148              // PAD + TT + PAD
#define BB   50
#define CC   4096
#define BC   (BB * CC)        // 204800 channels
#define NSEC 2
#define NBAND 2
#define BLK  32               // threads per block; each thread owns 2 channels

typedef unsigned long long u64;

// ---- packed f32x2 helpers (Blackwell sm_100+) ----
__device__ __forceinline__ u64 pk2(float lo, float hi) {
    u64 r; asm("mov.b64 %0, {%1, %2};" : "=l"(r) : "f"(lo), "f"(hi)); return r;
}
__device__ __forceinline__ u64 bcast2(float v) { return pk2(v, v); }
__device__ __forceinline__ void unpk2(u64 v, float& lo, float& hi) {
    asm("mov.b64 {%0, %1}, %2;" : "=f"(lo), "=f"(hi) : "l"(v));
}
__device__ __forceinline__ u64 fma2(u64 a, u64 b, u64 c) {
    u64 d; asm("fma.rn.f32x2 %0, %1, %2, %3;" : "=l"(d) : "l"(a), "l"(b), "l"(c)); return d;
}
__device__ __forceinline__ u64 mul2(u64 a, u64 b) {
    u64 d; asm("mul.rn.f32x2 %0, %1, %2;" : "=l"(d) : "l"(a), "l"(b)); return d;
}
__device__ __forceinline__ u64 add2(u64 a, u64 b) {
    u64 d; asm("add.rn.f32x2 %0, %1, %2;" : "=l"(d) : "l"(a), "l"(b)); return d;
}

struct FiltCoef {
    // [band][section]
    float b0[NBAND][NSEC];
    float b2[NBAND][NSEC];
    float a1[NBAND][NSEC];
    float a2[NBAND][NSEC];
    float zi0[NBAND][NSEC];
    float zi1[NBAND][NSEC];
};

// per-band, per-channel normalization stats (channel index = b*C + c)
__device__ float g_m2 [NBAND][BC];
__device__ float g_inv[NBAND][BC];

__global__ void __launch_bounds__(BLK)
filtfilt_kernel(const u64* __restrict__ x2, u64* __restrict__ out2, FiltCoef cf) {
    __shared__ u64 sm2[EXT * BLK];             // 37,888 bytes (< 48KB, no opt-in needed)
    const int tid  = threadIdx.x;
    const int chp  = blockIdx.x * BLK + tid;   // channel-pair index in [0, BC/2)
    const int band = blockIdx.y;
    u64* col = sm2 + tid;                      // thread-private column, stride BLK

    // ---- load input + build odd extension (packed) ----
    #pragma unroll 5
    for (int t = 0; t < TT; t++)
        col[(PAD + t) * BLK] = x2[(size_t)t * (BC / 2) + chp];

    const u64 n1  = bcast2(-1.0f);
    const u64 tx0 = add2(col[PAD * BLK], col[PAD * BLK]);                  // 2*x0
    const u64 txl = add2(col[(PAD + TT - 1) * BLK], col[(PAD + TT - 1) * BLK]);
    #pragma unroll 7
    for (int k = 1; k <= PAD; k++) {
        col[(PAD - k) * BLK]          = fma2(n1, col[(PAD + k) * BLK], tx0);
        col[(PAD + TT - 1 + k) * BLK] = fma2(n1, col[(PAD + TT - 1 - k) * BLK], txl);
    }

    const u64 b00 = bcast2(cf.b0[band][0]), b20 = bcast2(cf.b2[band][0]);
    const u64 na10 = bcast2(-cf.a1[band][0]), na20 = bcast2(-cf.a2[band][0]);
    const u64 b01 = bcast2(cf.b0[band][1]), b21 = bcast2(cf.b2[band][1]);
    const u64 na11 = bcast2(-cf.a1[band][1]), na21 = bcast2(-cf.a2[band][1]);
    const u64 zi00 = bcast2(cf.zi0[band][0]), zi10 = bcast2(cf.zi1[band][0]);
    const u64 zi01 = bcast2(cf.zi0[band][1]), zi11 = bcast2(cf.zi1[band][1]);

    // ---- forward pass (2 cascaded biquads, DF2T, packed 2 channels) ----
    {
        const u64 e0 = col[0];
        u64 z00 = mul2(zi00, e0), z01 = mul2(zi10, e0);
        u64 z10 = mul2(zi01, e0), z11 = mul2(zi11, e0);
        u64* p = col;
        #pragma unroll 4
        for (int t = 0; t < EXT; t++) {
            const u64 xt = *p;
            const u64 y0 = fma2(b00, xt, z00);
            z00 = fma2(na10, y0, z01);
            z01 = fma2(b20, xt, mul2(na20, y0));
            const u64 y1 = fma2(b01, y0, z10);
            z10 = fma2(na11, y1, z11);
            z11 = fma2(b21, y0, mul2(na21, y1));
            *p = y1;
            p += BLK;
        }
    }

    // ---- backward pass (filter reversed signal, in place) ----
    {
        const u64 yl = col[(EXT - 1) * BLK];
        u64 z00 = mul2(zi00, yl), z01 = mul2(zi10, yl);
        u64 z10 = mul2(zi01, yl), z11 = mul2(zi11, yl);
        u64* p = col + (EXT - 1) * BLK;
        #pragma unroll 4
        for (int t = 0; t < EXT; t++) {
            const u64 xt = *p;
            const u64 y0 = fma2(b00, xt, z00);
            z00 = fma2(na10, y0, z01);
            z01 = fma2(b20, xt, mul2(na20, y0));
            const u64 y1 = fma2(b01, y0, z10);
            z10 = fma2(na11, y1, z11);
            z11 = fma2(b21, y0, mul2(na21, y1));
            *p = y1;
            p -= BLK;
        }
    }

    // ---- first demean over T (per-channel), write yd, gather stats ----
    u64 s = 0;
    #pragma unroll 10
    for (int t = 0; t < TT; t++) s = add2(s, col[(PAD + t) * BLK]);
    float slo, shi; unpk2(s, slo, shi);
    const u64 nm = pk2(-slo * (1.0f / TT), -shi * (1.0f / TT));

    u64 s2 = 0;
    u64* ob = out2 + (size_t)band * TT * (BC / 2) + chp;
    #pragma unroll 10
    for (int t = 0; t < TT; t++) {
        const u64 yd = add2(col[(PAD + t) * BLK], nm);
        col[(PAD + t) * BLK] = yd;
        ob[(size_t)t * (BC / 2)] = yd;
        s2 = add2(s2, yd);
    }
    float s2lo, s2hi; unpk2(s2, s2lo, s2hi);
    const float m2lo = s2lo * (1.0f / TT), m2hi = s2hi * (1.0f / TT);
    const u64 nm2 = pk2(-m2lo, -m2hi);

    u64 vv = 0;
    #pragma unroll 10
    for (int t = 0; t < TT; t++) {
        const u64 d = add2(col[(PAD + t) * BLK], nm2);
        vv = fma2(d, d, vv);
    }
    float vlo, vhi; unpk2(vv, vlo, vhi);

    ((u64*)g_m2[band])[chp]  = pk2(m2lo, m2hi);
    ((u64*)g_inv[band])[chp] = pk2(rsqrtf(vlo * (1.0f / (TT - 1))),
                                   rsqrtf(vhi * (1.0f / (TT - 1))));
}

// out[band, t, b, c] = (yd - m2[band, t*C+c]) * inv_s[band, t*C+c]
// (stats indexed by TIME index t, mirroring the reference's broadcasting quirk; T==B)
__global__ void __launch_bounds__(256)
normalize_kernel(float4* __restrict__ out4) {
    const int idx4 = blockIdx.x * 256 + threadIdx.x;   // < NBAND*TT*BC/4
    const int c4   = idx4 & (CC / 4 - 1);
    const int rest = idx4 / (BC / 4);                  // band*TT + t
    const int t    = rest % TT;
    const int band = rest / TT;
    const int s4   = t * (CC / 4) + c4;                // stat index (channel b'=t, c)

    float4 v = out4[idx4];
    const float4 m = ((const float4*)g_m2[band])[s4];
    const float4 s = ((const float4*)g_inv[band])[s4];
    v.x = (v.x - m.x) * s.x;
    v.y = (v.y - m.y) * s.y;
    v.z = (v.z - m.z) * s.z;
    v.w = (v.w - m.w) * s.w;
    out4[idx4] = v;
}

// ---------------- host-side filter design (mirrors reference numpy code) ----------------
static void design_band(double w1, double w2, double sos[NSEC][6], double zi[NSEC][2]) {
    using cd = std::complex<double>;
    const double PI = 3.14159265358979323846;
    const double fs = 2.0;
    const double W1 = 2.0 * fs * tan(PI * w1 / fs);
    const double W2 = 2.0 * fs * tan(PI * w2 / fs);
    const double bw = W2 - W1;
    const double wo = sqrt(W1 * W2);

    cd p_bp[4];
    for (int k = 1; k <= 2; k++) {
        cd p = -std::exp(cd(0.0, PI * (2 * k - 1) / 4.0));
        cd plp = p * (bw / 2.0);
        cd disc = std::sqrt(plp * plp - cd(wo * wo, 0.0));
        p_bp[k - 1] = plp + disc;
        p_bp[k + 1] = plp - disc;
    }
    const double fs2 = 2.0 * fs;   // 4.0
    cd prod(1.0, 0.0);
    for (int i = 0; i < 4; i++) prod *= (cd(fs2, 0.0) - p_bp[i]);
    const double gain = bw * bw * fs2 * fs2 / prod.real();

    cd pos[2];
    int npos = 0;
    for (int i = 0; i < 4; i++) {
        cd pd = (cd(fs2, 0.0) + p_bp[i]) / (cd(fs2, 0.0) - p_bp[i]);
        if (pd.imag() > 0.0 && npos < 2) pos[npos++] = pd;
    }
    for (int s = 0; s < NSEC; s++) {
        const double g = (s == 0) ? gain : 1.0;
        sos[s][0] = g;  sos[s][1] = 0.0;  sos[s][2] = -g;
        sos[s][3] = 1.0;
        sos[s][4] = -2.0 * pos[s].real();
        sos[s][5] = std::norm(pos[s]);
    }
    // sosfilt_zi
    double scale = 1.0;
    for (int s = 0; s < NSEC; s++) {
        const double b0 = sos[s][0], b1 = sos[s][1], b2 = sos[s][2];
        const double a1 = sos[s][4], a2 = sos[s][5];
        const double B0 = b1 - a1 * b0;
        const double B1 = b2 - a2 * b0;
        const double det = 1.0 + a1 + a2;
        zi[s][0] = scale * (B0 + B1) / det;
        zi[s][1] = scale * ((1.0 + a1) * B1 - a2 * B0) / det;
        scale *= (b0 + b1 + b2) / (1.0 + a1 + a2);
    }
}

extern "C" void kernel_launch(void* const* d_in, const int* in_sizes, int n_in,
                              void* d_out, int out_size) {
    const u64* x2 = (const u64*)d_in[0];
    u64* out2 = (u64*)d_out;

    const double bands[NBAND][2] = { {0.05, 0.15}, {0.2, 0.4} };
    FiltCoef cf;
    for (int b = 0; b < NBAND; b++) {
        double sos[NSEC][6], zi[NSEC][2];
        design_band(bands[b][0], bands[b][1], sos, zi);
        for (int s = 0; s < NSEC; s++) {
            cf.b0[b][s]  = (float)sos[s][0];
            cf.b2[b][s]  = (float)sos[s][2];
            cf.a1[b][s]  = (float)sos[s][4];
            cf.a2[b][s]  = (float)sos[s][5];
            cf.zi0[b][s] = (float)zi[s][0];
            cf.zi1[b][s] = (float)zi[s][1];
        }
    }

    dim3 grid1(BC / 2 / BLK, NBAND);                       // 3200 x 2
    filtfilt_kernel<<<grid1, BLK>>>(x2, out2, cf);

    const int total4 = NBAND * TT * BC / 4;                // 5,120,000
    normalize_kernel<<<total4 / 256, 256>>>((float4*)d_out);
}

// round 7
// speedup vs baseline: 2.4255x; 2.1686x over previous
#include <cuda_runtime.h>
#include <cmath>
#include <complex>
#include <cstring>

// Problem constants
#define TT   50
#define PAD  49
#define EXT  148              // PAD + TT + PAD
#define BB   50
#define CC   4096
#define BC   (BB * CC)        // 204800 channels
#define NSEC 2
#define NBAND 2
#define BLK  128              // threads per block; one channel per thread, zero smem

struct FiltCoef {
    // [band][section]
    float b0[NBAND][NSEC];
    float b2[NBAND][NSEC];
    float a1[NBAND][NSEC];
    float a2[NBAND][NSEC];
    float zi0[NBAND][NSEC];
    float zi1[NBAND][NSEC];
};

// per-band, per-channel normalization stats (channel index = b*C + c)
__device__ float g_m2 [NBAND][BC];
__device__ float g_inv[NBAND][BC];

__global__ void __launch_bounds__(BLK)
filtfilt_kernel(const float* __restrict__ x, float* __restrict__ out, FiltCoef cf) {
    const int ch   = blockIdx.x * BLK + threadIdx.x;  // channel in [0, BC)
    const int band = blockIdx.y;
    const float* xc = x + ch;

    const float b00 = cf.b0[band][0], b20 = cf.b2[band][0];
    const float a10 = cf.a1[band][0], a20 = cf.a2[band][0];
    const float b01 = cf.b0[band][1], b21 = cf.b2[band][1];
    const float a11 = cf.a1[band][1], a21 = cf.a2[band][1];

    // y for ext indices [PAD, EXT) lives in registers (fully unrolled indexing)
    float arr[EXT - PAD];   // 99 floats

    const float x0 = xc[0];
    const float xl = xc[(size_t)(TT - 1) * BC];
    const float tx0 = 2.0f * x0;
    const float txl = 2.0f * xl;

    // ---- forward pass (2 cascaded biquads, DF2T) over the odd extension ----
    {
        const float e0 = tx0 - xc[(size_t)PAD * BC];   // ext[0] = 2*x0 - x[PAD]
        float z00 = cf.zi0[band][0] * e0, z01 = cf.zi1[band][0] * e0;
        float z10 = cf.zi0[band][1] * e0, z11 = cf.zi1[band][1] * e0;

        // left mirror: t = 0..PAD-1, xt = 2*x0 - x[PAD-t]  (state only, no storage)
        #pragma unroll
        for (int t = 0; t < PAD; t++) {
            const float xt = tx0 - xc[(size_t)(PAD - t) * BC];
            const float y0 = fmaf(b00, xt, z00);
            z00 = fmaf(-a10, y0, z01);
            z01 = fmaf(b20, xt, -a20 * y0);
            const float y1 = fmaf(b01, y0, z10);
            z10 = fmaf(-a11, y1, z11);
            z11 = fmaf(b21, y0, -a21 * y1);
        }
        // central: t = PAD..PAD+TT-1, xt = x[t-PAD], store y
        #pragma unroll
        for (int t = 0; t < TT; t++) {
            const float xt = xc[(size_t)t * BC];
            const float y0 = fmaf(b00, xt, z00);
            z00 = fmaf(-a10, y0, z01);
            z01 = fmaf(b20, xt, -a20 * y0);
            const float y1 = fmaf(b01, y0, z10);
            z10 = fmaf(-a11, y1, z11);
            z11 = fmaf(b21, y0, -a21 * y1);
            arr[t] = y1;
        }
        // right mirror: t = PAD+TT..EXT-1, xt = 2*xl - x[EXT-1-t], store y
        #pragma unroll
        for (int k = 1; k <= PAD; k++) {
            const float xt = txl - xc[(size_t)(TT - 1 - k) * BC];
            const float y0 = fmaf(b00, xt, z00);
            z00 = fmaf(-a10, y0, z01);
            z01 = fmaf(b20, xt, -a20 * y0);
            const float y1 = fmaf(b01, y0, z10);
            z10 = fmaf(-a11, y1, z11);
            z11 = fmaf(b21, y0, -a21 * y1);
            arr[TT - 1 + k] = y1;
        }
    }

    // ---- backward pass: filter reversed y from ext index EXT-1 down to PAD ----
    // (steps below PAD only produce discarded outputs and cannot affect these;
    //  backward state propagates right-to-left, so we stop at PAD)
    {
        const float e = arr[EXT - PAD - 1];   // y at ext index EXT-1
        float z00 = cf.zi0[band][0] * e, z01 = cf.zi1[band][0] * e;
        float z10 = cf.zi0[band][1] * e, z11 = cf.zi1[band][1] * e;
        #pragma unroll
        for (int i = 0; i < EXT - PAD; i++) {   // slot 98 down to 0
            const int s = EXT - PAD - 1 - i;
            const float xt = arr[s];
            const float y0 = fmaf(b00, xt, z00);
            z00 = fmaf(-a10, y0, z01);
            z01 = fmaf(b20, xt, -a20 * y0);
            const float y1 = fmaf(b01, y0, z10);
            z10 = fmaf(-a11, y1, z11);
            z11 = fmaf(b21, y0, -a21 * y1);
            if (s < TT) arr[s] = y1;   // central outputs, correct time order
        }
    }

    // ---- first demean over T (per-channel), write yd, gather stats ----
    float s = 0.0f;
    #pragma unroll
    for (int t = 0; t < TT; t++) s += arr[t];
    const float m = s * (1.0f / TT);

    float s2 = 0.0f;
    float* ob = out + (size_t)band * TT * BC + ch;
    #pragma unroll
    for (int t = 0; t < TT; t++) {
        const float yd = arr[t] - m;
        arr[t] = yd;
        ob[(size_t)t * BC] = yd;
        s2 += yd;
    }
    const float m2 = s2 * (1.0f / TT);

    float v = 0.0f;
    #pragma unroll
    for (int t = 0; t < TT; t++) {
        const float d = arr[t] - m2;
        v = fmaf(d, d, v);
    }
    g_m2 [band][ch] = m2;
    g_inv[band][ch] = rsqrtf(v * (1.0f / (TT - 1)));
}

// out[band, t, b, c] = (yd - m2[band, t*C+c]) * inv_s[band, t*C+c]
// (stats indexed by TIME index t, mirroring the reference's broadcasting quirk; T==B)
// Each thread handles the same (t,b,c) position in BOTH bands (shared index math, 2x MLP).
__global__ void __launch_bounds__(256)
normalize_kernel(float4* __restrict__ out4) {
    const int idx4 = blockIdx.x * 256 + threadIdx.x;   // < TT*BC/4 (one band's worth)
    const int c4   = idx4 & (CC / 4 - 1);
    const int t    = idx4 / (BC / 4);                  // time index (band 0 layout)
    const int s4   = t * (CC / 4) + c4;                // stat index (channel b'=t, c)
    const int HALF = TT * BC / 4;                      // elements per band / 4

    float4 v0 = out4[idx4];
    float4 v1 = out4[idx4 + HALF];
    const float4 m0 = ((const float4*)g_m2[0])[s4];
    const float4 s0 = ((const float4*)g_inv[0])[s4];
    const float4 m1 = ((const float4*)g_m2[1])[s4];
    const float4 s1 = ((const float4*)g_inv[1])[s4];
    v0.x = (v0.x - m0.x) * s0.x;  v1.x = (v1.x - m1.x) * s1.x;
    v0.y = (v0.y - m0.y) * s0.y;  v1.y = (v1.y - m1.y) * s1.y;
    v0.z = (v0.z - m0.z) * s0.z;  v1.z = (v1.z - m1.z) * s1.z;
    v0.w = (v0.w - m0.w) * s0.w;  v1.w = (v1.w - m1.w) * s1.w;
    out4[idx4]        = v0;
    out4[idx4 + HALF] = v1;
}

// ---------------- host-side filter design (mirrors reference numpy code) ----------------
static void design_band(double w1, double w2, double sos[NSEC][6], double zi[NSEC][2]) {
    using cd = std::complex<double>;
    const double PI = 3.14159265358979323846;
    const double fs = 2.0;
    const double W1 = 2.0 * fs * tan(PI * w1 / fs);
    const double W2 = 2.0 * fs * tan(PI * w2 / fs);
    const double bw = W2 - W1;
    const double wo = sqrt(W1 * W2);

    cd p_bp[4];
    for (int k = 1; k <= 2; k++) {
        cd p = -std::exp(cd(0.0, PI * (2 * k - 1) / 4.0));
        cd plp = p * (bw / 2.0);
        cd disc = std::sqrt(plp * plp - cd(wo * wo, 0.0));
        p_bp[k - 1] = plp + disc;
        p_bp[k + 1] = plp - disc;
    }
    const double fs2 = 2.0 * fs;   // 4.0
    cd prod(1.0, 0.0);
    for (int i = 0; i < 4; i++) prod *= (cd(fs2, 0.0) - p_bp[i]);
    const double gain = bw * bw * fs2 * fs2 / prod.real();

    cd pos[2];
    int npos = 0;
    for (int i = 0; i < 4; i++) {
        cd pd = (cd(fs2, 0.0) + p_bp[i]) / (cd(fs2, 0.0) - p_bp[i]);
        if (pd.imag() > 0.0 && npos < 2) pos[npos++] = pd;
    }
    for (int s = 0; s < NSEC; s++) {
        const double g = (s == 0) ? gain : 1.0;
        sos[s][0] = g;  sos[s][1] = 0.0;  sos[s][2] = -g;
        sos[s][3] = 1.0;
        sos[s][4] = -2.0 * pos[s].real();
        sos[s][5] = std::norm(pos[s]);
    }
    // sosfilt_zi
    double scale = 1.0;
    for (int s = 0; s < NSEC; s++) {
        const double b0 = sos[s][0], b1 = sos[s][1], b2 = sos[s][2];
        const double a1 = sos[s][4], a2 = sos[s][5];
        const double B0 = b1 - a1 * b0;
        const double B1 = b2 - a2 * b0;
        const double det = 1.0 + a1 + a2;
        zi[s][0] = scale * (B0 + B1) / det;
        zi[s][1] = scale * ((1.0 + a1) * B1 - a2 * B0) / det;
        scale *= (b0 + b1 + b2) / (1.0 + a1 + a2);
    }
}

extern "C" void kernel_launch(void* const* d_in, const int* in_sizes, int n_in,
                              void* d_out, int out_size) {
    const float* x = (const float*)d_in[0];
    float* out = (float*)d_out;

    const double bands[NBAND][2] = { {0.05, 0.15}, {0.2, 0.4} };
    FiltCoef cf;
    for (int b = 0; b < NBAND; b++) {
        double sos[NSEC][6], zi[NSEC][2];
        design_band(bands[b][0], bands[b][1], sos, zi);
        for (int s = 0; s < NSEC; s++) {
            cf.b0[b][s]  = (float)sos[s][0];
            cf.b2[b][s]  = (float)sos[s][2];
            cf.a1[b][s]  = (float)sos[s][4];
            cf.a2[b][s]  = (float)sos[s][5];
            cf.zi0[b][s] = (float)zi[s][0];
            cf.zi1[b][s] = (float)zi[s][1];
        }
    }

    dim3 grid1(BC / BLK, NBAND);                 // 1600 x 2
    filtfilt_kernel<<<grid1, BLK>>>(x, out, cf);

    const int q4 = TT * BC / 4;                  // one band's float4 count
    normalize_kernel<<<q4 / 256, 256>>>((float4*)d_out);
}